// round 2
// baseline (speedup 1.0000x reference)
#include <cuda_runtime.h>
#include <cuda_bf16.h>
#include <math.h>

// Problem constants
#define B   256
#define S   512
#define H   256
#define OUT 3
#define NSTEP 64
#define G4  1024          // 4*H
#define INW 259           // OUT + H
#define KP  528           // padded K (515 -> 33 tiles of 16)
#define KT  33

#define PRED_SZ (B*NSTEP*OUT)          // 49152
#define HID_OFF PRED_SZ                // 49152
#define ATTN_OFF (PRED_SZ + B*H)       // 114688

// ---------------- scratch (device globals; no allocation) ----------------
__device__ float g_PT[H*H];        // P^T : PT[j*H + h] = sum_g Ua[g,h]*Wa[g,j]
__device__ float g_q[H];           // Ua^T @ ba
__device__ float g_u[H];           // Wa^T @ bua
__device__ float g_dscal;          // bua . ba
__device__ float g_Wc[KP*G4];      // packed weights, k-major: Wc[k*1024 + r]
__device__ float g_bias[G4];       // b_ih + b_hh
__device__ float g_XT[KP*B];       // X^T: rows 0..255 ctx, 256..511 h, 512..514 x_in, rest 0
__device__ float g_c[B*H];         // cell state
__device__ float g_gates[4][B*G4]; // 4 K-split partial gate buffers, layout [b*1024 + r]

// ---------------- helpers ----------------
__device__ __forceinline__ float sigmoidf_(float x){ return 1.f/(1.f+expf(-x)); }

__device__ __forceinline__ void cpasync16(void* sdst, const void* gsrc){
    unsigned sa = (unsigned)__cvta_generic_to_shared(sdst);
    asm volatile("cp.async.cg.shared.global [%0], [%1], 16;\n" :: "r"(sa), "l"(gsrc) : "memory");
}
__device__ __forceinline__ void cp_commit(){ asm volatile("cp.async.commit_group;\n" ::: "memory"); }
__device__ __forceinline__ void cp_wait0(){ asm volatile("cp.async.wait_group 0;\n" ::: "memory"); }
__device__ __forceinline__ void cp_wait1(){ asm volatile("cp.async.wait_group 1;\n" ::: "memory"); }

// block-wide sum over 256 threads; broadcast result. red must have >= 33 floats.
__device__ __forceinline__ float blockSum256(float v, float* red){
    #pragma unroll
    for (int o = 16; o > 0; o >>= 1) v += __shfl_down_sync(0xffffffffu, v, o);
    int w = threadIdx.x >> 5;
    if ((threadIdx.x & 31) == 0) red[w] = v;
    __syncthreads();
    if (threadIdx.x < 32){
        float t = (threadIdx.x < 8) ? red[threadIdx.x] : 0.f;
        #pragma unroll
        for (int o = 4; o > 0; o >>= 1) t += __shfl_down_sync(0xffffffffu, t, o);
        if (threadIdx.x == 0) red[32] = t;
    }
    __syncthreads();
    return red[32];
}

// ---------------- precompute 1: PT, q, u, d ----------------
__global__ void __launch_bounds__(256) prep_pt(const float* __restrict__ Wa,
                                               const float* __restrict__ ba,
                                               const float* __restrict__ Ua,
                                               const float* __restrict__ bua){
    int j = blockIdx.x, h = threadIdx.x;
    float acc = 0.f;
    for (int g = 0; g < H; g++) acc += Ua[g*H + h] * Wa[g*H + j];
    g_PT[j*H + h] = acc;
    if (j == 0){
        float a = 0.f;
        for (int g = 0; g < H; g++) a += Ua[g*H + h] * ba[g];
        g_q[h] = a;
    }
    if (j == 1){
        float a = 0.f;
        for (int g = 0; g < H; g++) a += bua[g] * Wa[g*H + h];
        g_u[h] = a;
    }
    if (j == 2 && h == 0){
        float a = 0.f;
        for (int g = 0; g < H; g++) a += bua[g] * ba[g];
        g_dscal = a;
    }
}

// ---------------- precompute 2: pack weights + bias + zero pads ----------------
__global__ void __launch_bounds__(256) prep_pack(const float* __restrict__ W_ih,
                                                 const float* __restrict__ W_hh,
                                                 const float* __restrict__ b_ih,
                                                 const float* __restrict__ b_hh){
    int k = blockIdx.x, t = threadIdx.x;
    #pragma unroll
    for (int m = 0; m < 4; m++){
        int r = t + m*256;
        float v;
        if (k < 256)      v = W_ih[r*INW + 3 + k];       // ctx part
        else if (k < 512) v = W_hh[r*H + (k - 256)];     // h part
        else if (k < 515) v = W_ih[r*INW + (k - 512)];   // x_in part
        else              v = 0.f;                       // pad
        g_Wc[k*G4 + r] = v;
    }
    if (k >= 515) g_XT[k*B + t] = 0.f;                   // zero pad rows of X^T
    if (k < 4){
        int r = k*256 + t;
        g_bias[r] = b_ih[r] + b_hh[r];
    }
}

// ---------------- ATT kernel: cell + pred + vq + online-softmax attention ----------------
// grid = 256 (one block per batch), 256 threads
// dynamic smem layout (floats):
//   buf[2][32][256] : 16384
//   scores[512]     : +512   (16384)
//   vq[256]         : +256   (16896)
//   hsm[256]        : +256   (17152)
//   psm[32]         : +32    (17408)
//   red[64]         : +64    (17440)
// total 17504 floats = 70016 bytes
#define ATT_SMEM_FLOATS 17504
#define ATT_SMEM_BYTES (ATT_SMEM_FLOATS*4)

__global__ void __launch_bounds__(256) att_step(const float* __restrict__ enc,
                                                const float* __restrict__ eh,
                                                const float* __restrict__ ec,
                                                const float* __restrict__ Wo,
                                                const float* __restrict__ bo,
                                                float* __restrict__ out,
                                                int step, int last){
    extern __shared__ float sm[];
    float* buf    = sm;
    float* scores = sm + 16384;
    float* vq     = sm + 16896;
    float* hsm    = sm + 17152;
    float* psm    = sm + 17408;
    float* red    = sm + 17440;

    const int tid = threadIdx.x;
    const int b   = blockIdx.x;

    // ---- Phase 0: LSTM cell (consumes gates of previous step) ----
    float h;
    if (step == 0){
        h = eh[b*H + tid];
        g_c[b*H + tid] = ec[b*H + tid];
        if (tid < 3) g_XT[(512 + tid)*B + b] = 0.f;   // x_in = SOS = 0
    } else {
        int gi = b*G4 + tid;
        float zi = g_gates[0][gi]       + g_gates[1][gi]       + g_gates[2][gi]       + g_gates[3][gi];
        float zf = g_gates[0][gi + 256] + g_gates[1][gi + 256] + g_gates[2][gi + 256] + g_gates[3][gi + 256];
        float zg = g_gates[0][gi + 512] + g_gates[1][gi + 512] + g_gates[2][gi + 512] + g_gates[3][gi + 512];
        float zo = g_gates[0][gi + 768] + g_gates[1][gi + 768] + g_gates[2][gi + 768] + g_gates[3][gi + 768];
        float co = g_c[b*H + tid];
        float cn = sigmoidf_(zf)*co + sigmoidf_(zi)*tanhf(zg);
        h = sigmoidf_(zo)*tanhf(cn);
        g_c[b*H + tid] = cn;
    }
    hsm[tid] = h;
    if (!last) g_XT[(256 + tid)*B + b] = h;
    __syncthreads();

    // ---- pred = Wo @ h + bo  (for previous step's output, feeds x_in) ----
    if (step > 0){
        #pragma unroll
        for (int r = 0; r < 3; r++){
            float p = blockSum256(Wo[r*H + tid] * h, red);
            if (tid == 0){
                float pr = p + bo[r];
                out[(size_t)b*(NSTEP*OUT) + (step - 1)*OUT + r] = pr;
                if (!last) g_XT[(512 + r)*B + b] = pr;
            }
        }
    }
    if (last){
        out[HID_OFF + b*H + tid] = h;   // decoder_hidden
        return;
    }

    // ---- Phase 1: vq = P @ h + q ; cb = u.h + d ----
    {
        float a0 = g_q[tid], a1 = 0.f, a2 = 0.f, a3 = 0.f;
        #pragma unroll 4
        for (int j = 0; j < H; j += 4){
            a0 += g_PT[(j+0)*H + tid] * hsm[j+0];
            a1 += g_PT[(j+1)*H + tid] * hsm[j+1];
            a2 += g_PT[(j+2)*H + tid] * hsm[j+2];
            a3 += g_PT[(j+3)*H + tid] * hsm[j+3];
        }
        vq[tid] = (a0 + a1) + (a2 + a3);
    }
    float cb = blockSum256(g_u[tid]*h, red) + g_dscal;
    // blockSum's internal barriers also make vq[] visible to all threads here.

    // ---- Phase 2: stream enc[b] once, online softmax + ctx ----
    const size_t encb = (size_t)b * S * H;
    float ctx = 0.f, m = -1e30f, denom = 0.f;
    const int wid = tid >> 5, lane = tid & 31;

    // issue chunk 0
    {
        const float4* src = (const float4*)(enc + encb);
        float4* dst = (float4*)buf;
        #pragma unroll
        for (int i = 0; i < 8; i++) cpasync16(dst + tid + i*256, src + tid + i*256);
        cp_commit();
    }

    for (int c = 0; c < 16; c++){
        if (c < 15){
            const float4* src = (const float4*)(enc + encb + (size_t)(c+1)*32*H);
            float4* dst = (float4*)(buf + ((c+1)&1)*8192);
            #pragma unroll
            for (int i = 0; i < 8; i++) cpasync16(dst + tid + i*256, src + tid + i*256);
            cp_commit();
            cp_wait1();
        } else {
            cp_wait0();
        }
        __syncthreads();
        const float* eb = buf + (c&1)*8192;

        // scores for 32 rows: warp w handles rows w*4 .. w*4+3
        #pragma unroll
        for (int rr = 0; rr < 4; rr++){
            int sl = wid*4 + rr;
            const float* row = eb + sl*H;
            float d = 0.f;
            #pragma unroll
            for (int k = 0; k < 8; k++) d += row[lane + k*32] * vq[lane + k*32];
            #pragma unroll
            for (int o = 16; o > 0; o >>= 1) d += __shfl_down_sync(0xffffffffu, d, o);
            if (lane == 0) scores[c*32 + sl] = d + cb;
        }
        __syncthreads();

        // chunk max (warp 0)
        if (tid < 32){
            float v = scores[c*32 + tid];
            #pragma unroll
            for (int o = 16; o > 0; o >>= 1) v = fmaxf(v, __shfl_down_sync(0xffffffffu, v, o));
            if (tid == 0) red[33] = v;
        }
        __syncthreads();
        float mn = fmaxf(m, red[33]);

        // p + chunk sum (warp 0)
        if (tid < 32){
            float p = expf(scores[c*32 + tid] - mn);
            psm[tid] = p;
            #pragma unroll
            for (int o = 16; o > 0; o >>= 1) p += __shfl_down_sync(0xffffffffu, p, o);
            if (tid == 0) red[34] = p;
        }
        __syncthreads();
        float rs = expf(m - mn);
        ctx   = ctx * rs;
        denom = denom * rs + red[34];
        m = mn;

        // ctx accumulation (thread tid owns h = tid)
        float c0 = 0.f, c1 = 0.f;
        #pragma unroll
        for (int s = 0; s < 32; s += 2){
            c0 += psm[s]   * eb[s*H + tid];
            c1 += psm[s+1] * eb[(s+1)*H + tid];
        }
        ctx += c0 + c1;
        __syncthreads();   // before buffer reuse / psm overwrite
    }

    // ---- write attentions + normalized ctx ----
    float inv = 1.f / denom;
    size_t abase = (size_t)ATTN_OFF + ((size_t)b*NSTEP + step)*S;
    out[abase + tid]       = expf(scores[tid]       - m) * inv;
    out[abase + tid + 256] = expf(scores[tid + 256] - m) * inv;
    g_XT[tid*B + b] = ctx * inv;     // FIX: normalize context by softmax denom
}

// ---------------- gates GEMM: C[r,b] = sum_k Wc[k,r] * XT[k,b], 4-way K split ----------------
// grid (16, 4, 4): 64x64 output tiles, z = K split. 256 threads, 4x4 microtile.
__global__ void __launch_bounds__(256) gates_gemm(){
    const int rt = blockIdx.x, bt = blockIdx.y, z = blockIdx.z;
    const int starts[5] = {0, 9, 17, 25, 33};
    const int t0 = starts[z], t1 = starts[z+1];

    __shared__ float As[2][16][68];
    __shared__ float Bs[2][16][68];

    const int tid = threadIdx.x;
    const int tx = tid & 15, ty = tid >> 4;
    const int lk = tid >> 4, lx = (tid & 15) * 4;

    float4 pa, pb;
    {
        int k = t0*16 + lk;
        pa = *(const float4*)&g_Wc[k*G4 + rt*64 + lx];
        pb = *(const float4*)&g_XT[k*B  + bt*64 + lx];
    }
    *(float4*)&As[0][lk][lx] = pa;
    *(float4*)&Bs[0][lk][lx] = pb;

    float acc[4][4];
    #pragma unroll
    for (int i = 0; i < 4; i++)
        #pragma unroll
        for (int j = 0; j < 4; j++) acc[i][j] = 0.f;

    const int nt = t1 - t0;
    for (int it = 0; it < nt; it++){
        __syncthreads();
        if (it + 1 < nt){
            int k = (t0 + it + 1)*16 + lk;
            pa = *(const float4*)&g_Wc[k*G4 + rt*64 + lx];
            pb = *(const float4*)&g_XT[k*B  + bt*64 + lx];
        }
        int cur = it & 1;
        #pragma unroll
        for (int kk = 0; kk < 16; kk++){
            float4 fa = *(float4*)&As[cur][kk][ty*4];
            float4 fb = *(float4*)&Bs[cur][kk][tx*4];
            acc[0][0] += fa.x*fb.x; acc[0][1] += fa.x*fb.y; acc[0][2] += fa.x*fb.z; acc[0][3] += fa.x*fb.w;
            acc[1][0] += fa.y*fb.x; acc[1][1] += fa.y*fb.y; acc[1][2] += fa.y*fb.z; acc[1][3] += fa.y*fb.w;
            acc[2][0] += fa.z*fb.x; acc[2][1] += fa.z*fb.y; acc[2][2] += fa.z*fb.z; acc[2][3] += fa.z*fb.w;
            acc[3][0] += fa.w*fb.x; acc[3][1] += fa.w*fb.y; acc[3][2] += fa.w*fb.z; acc[3][3] += fa.w*fb.w;
        }
        if (it + 1 < nt){
            int nxt = cur ^ 1;
            *(float4*)&As[nxt][lk][lx] = pa;
            *(float4*)&Bs[nxt][lk][lx] = pb;
        }
    }

    float* G = g_gates[z];
    const int r0 = rt*64 + ty*4;
    const int b0 = bt*64 + tx*4;
    #pragma unroll
    for (int j = 0; j < 4; j++){
        float4 v = make_float4(acc[0][j], acc[1][j], acc[2][j], acc[3][j]);
        if (z == 0){
            v.x += g_bias[r0];     v.y += g_bias[r0 + 1];
            v.z += g_bias[r0 + 2]; v.w += g_bias[r0 + 3];
        }
        *(float4*)&G[(size_t)(b0 + j)*G4 + r0] = v;
    }
}

// ---------------- launch ----------------
extern "C" void kernel_launch(void* const* d_in, const int* in_sizes, int n_in,
                              void* d_out, int out_size){
    const float* enc = (const float*)d_in[0];
    const float* eh  = (const float*)d_in[1];
    const float* ec  = (const float*)d_in[2];
    const float* Wa  = (const float*)d_in[3];
    const float* ba  = (const float*)d_in[4];
    const float* Ua  = (const float*)d_in[5];
    const float* bua = (const float*)d_in[6];
    const float* Wih = (const float*)d_in[7];
    const float* Whh = (const float*)d_in[8];
    const float* bih = (const float*)d_in[9];
    const float* bhh = (const float*)d_in[10];
    const float* Wo  = (const float*)d_in[11];
    const float* bo  = (const float*)d_in[12];
    float* out = (float*)d_out;

    cudaFuncSetAttribute(att_step, cudaFuncAttributeMaxDynamicSharedMemorySize, ATT_SMEM_BYTES);

    prep_pt<<<256, 256>>>(Wa, ba, Ua, bua);
    prep_pack<<<KP, 256>>>(Wih, Whh, bih, bhh);

    for (int step = 0; step <= NSTEP; step++){
        att_step<<<B, 256, ATT_SMEM_BYTES>>>(enc, eh, ec, Wo, bo, out, step, step == NSTEP);
        if (step < NSTEP){
            gates_gemm<<<dim3(16, 4, 4), 256>>>();
        }
    }
}

// round 3
// speedup vs baseline: 1.1386x; 1.1386x over previous
#include <cuda_runtime.h>
#include <cuda_bf16.h>
#include <math.h>

// Problem constants
#define B   256
#define S   512
#define H   256
#define OUT 3
#define NSTEP 64
#define G4  1024          // 4*H
#define INW 259           // OUT + H
#define KP  528           // padded K (515 -> 33 tiles of 16)
#define NSPLIT 8

#define PRED_SZ (B*NSTEP*OUT)          // 49152
#define HID_OFF PRED_SZ                // 49152
#define ATTN_OFF (PRED_SZ + B*H)       // 114688

// ---------------- scratch (device globals; no allocation) ----------------
__device__ float g_PT[H*H];        // P^T : PT[j*H + h] = sum_g Ua[g,h]*Wa[g,j]
__device__ float g_q[H];           // Ua^T @ ba
__device__ float g_u[H];           // Wa^T @ bua
__device__ float g_dscal;          // bua . ba
__device__ float g_Wc[KP*G4];      // packed weights, k-major: Wc[k*1024 + r]
__device__ float g_bias[G4];       // b_ih + b_hh
__device__ float g_XT[KP*B];       // X^T: rows 0..255 ctx, 256..511 h, 512..514 x_in, rest 0
__device__ float g_c[B*H];         // cell state
__device__ float g_gates[NSPLIT][B*G4]; // K-split partial gate buffers, layout [b*1024 + r]

// ---------------- helpers ----------------
__device__ __forceinline__ float sigmoidf_(float x){ return 1.f/(1.f+expf(-x)); }

__device__ __forceinline__ void cpasync16(void* sdst, const void* gsrc){
    unsigned sa = (unsigned)__cvta_generic_to_shared(sdst);
    asm volatile("cp.async.cg.shared.global [%0], [%1], 16;\n" :: "r"(sa), "l"(gsrc) : "memory");
}
__device__ __forceinline__ void cp_commit(){ asm volatile("cp.async.commit_group;\n" ::: "memory"); }
__device__ __forceinline__ void cp_wait2(){ asm volatile("cp.async.wait_group 2;\n" ::: "memory"); }
__device__ __forceinline__ void barg(int id){ asm volatile("bar.sync %0, 256;" :: "r"(id) : "memory"); }

// ---------------- precompute 1a: PT ----------------
__global__ void __launch_bounds__(256) prep_pt(const float* __restrict__ Wa,
                                               const float* __restrict__ Ua){
    int j = blockIdx.x, h = threadIdx.x;
    float acc = 0.f;
    for (int g = 0; g < H; g++) acc += Ua[g*H + h] * Wa[g*H + j];
    g_PT[j*H + h] = acc;
}

// ---------------- precompute 1b: q, u, d ----------------
__global__ void __launch_bounds__(256) prep_vec(const float* __restrict__ Wa,
                                                const float* __restrict__ ba,
                                                const float* __restrict__ Ua,
                                                const float* __restrict__ bua){
    int h = threadIdx.x;
    float a = 0.f, c = 0.f;
    for (int g = 0; g < H; g++){
        a += Ua[g*H + h] * ba[g];
        c += bua[g] * Wa[g*H + h];
    }
    g_q[h] = a;
    g_u[h] = c;
    if (h == 0){
        float d = 0.f;
        for (int g = 0; g < H; g++) d += bua[g] * ba[g];
        g_dscal = d;
    }
}

// ---------------- precompute 2: pack weights + bias + zero pads ----------------
__global__ void __launch_bounds__(256) prep_pack(const float* __restrict__ W_ih,
                                                 const float* __restrict__ W_hh,
                                                 const float* __restrict__ b_ih,
                                                 const float* __restrict__ b_hh){
    int k = blockIdx.x, t = threadIdx.x;
    #pragma unroll
    for (int m = 0; m < 4; m++){
        int r = t + m*256;
        float v;
        if (k < 256)      v = W_ih[r*INW + 3 + k];       // ctx part
        else if (k < 512) v = W_hh[r*H + (k - 256)];     // h part
        else if (k < 515) v = W_ih[r*INW + (k - 512)];   // x_in part
        else              v = 0.f;                       // pad
        g_Wc[k*G4 + r] = v;
    }
    if (k >= 515) g_XT[k*B + t] = 0.f;                   // zero pad rows of X^T
    if (k < 4){
        int r = k*256 + t;
        g_bias[r] = b_ih[r] + b_hh[r];
    }
}

// ---------------- ATT kernel ----------------
// grid = 256 (one block per batch), 512 threads (2 groups of 256, split S)
// dynamic smem (floats):
//   buf   [2 groups][3 bufs][4096]   : 24576   (16-row fp32 chunks, depth-3 ring)
//   scores[512]                      : 24576
//   vq    [256]                      : 25088
//   sh512 [512]  (vq partials / ctx) : 25344
//   hsm   [256]                      : 25856
//   psm   [2][16]                    : 26112
//   red   [64]                       : 26144
//   stats [8]                        : 26208
#define ATT_SMEM_FLOATS 26216
#define ATT_SMEM_BYTES (ATT_SMEM_FLOATS*4)

__global__ void __launch_bounds__(512) att_step(const float* __restrict__ enc,
                                                const float* __restrict__ eh,
                                                const float* __restrict__ ec,
                                                const float* __restrict__ Wo,
                                                const float* __restrict__ bo,
                                                float* __restrict__ out,
                                                int step, int last){
    extern __shared__ float sm[];
    float* scores = sm + 24576;
    float* vq     = sm + 25088;
    float* sh512  = sm + 25344;
    float* hsm    = sm + 25856;
    float* psm    = sm + 26112;
    float* red    = sm + 26144;
    float* stats  = sm + 26208;

    const int tid  = threadIdx.x;
    const int g    = tid >> 8;
    const int lt   = tid & 255;
    const int wid  = tid >> 5;
    const int lane = tid & 31;
    const int b    = blockIdx.x;

    // ---- Phase 0: LSTM cell (threads 0..255) ----
    float h = 0.f;
    if (tid < 256){
        if (step == 0){
            h = eh[b*H + tid];
            g_c[b*H + tid] = ec[b*H + tid];
            if (tid < 3) g_XT[(512 + tid)*B + b] = 0.f;   // x_in = SOS = 0
        } else {
            float zi = 0.f, zf = 0.f, zg = 0.f, zo = 0.f;
            #pragma unroll
            for (int z = 0; z < NSPLIT; z++){
                const float* G = g_gates[z] + b*G4 + tid;
                zi += G[0]; zf += G[256]; zg += G[512]; zo += G[768];
            }
            float co = g_c[b*H + tid];
            float cn = sigmoidf_(zf)*co + sigmoidf_(zi)*tanhf(zg);
            h = sigmoidf_(zo)*tanhf(cn);
            g_c[b*H + tid] = cn;
        }
        hsm[tid] = h;
        if (!last) g_XT[(256 + tid)*B + b] = h;
    }
    __syncthreads();

    // ---- pred (3 rows of Wo) + cb = u.h, all in one reduction round ----
    {
        float v0 = 0.f, v1 = 0.f, v2 = 0.f, v3 = 0.f;
        if (tid < 256){
            float hh = h;
            v0 = Wo[tid]       * hh;
            v1 = Wo[256 + tid] * hh;
            v2 = Wo[512 + tid] * hh;
            v3 = g_u[tid]      * hh;
        }
        #pragma unroll
        for (int o = 16; o > 0; o >>= 1){
            v0 += __shfl_down_sync(0xffffffffu, v0, o);
            v1 += __shfl_down_sync(0xffffffffu, v1, o);
            v2 += __shfl_down_sync(0xffffffffu, v2, o);
            v3 += __shfl_down_sync(0xffffffffu, v3, o);
        }
        if (lane == 0){ red[wid*4] = v0; red[wid*4+1] = v1; red[wid*4+2] = v2; red[wid*4+3] = v3; }
        __syncthreads();
        if (tid < 8){
            float a0 = red[tid*4], a1 = red[tid*4+1], a2 = red[tid*4+2], a3 = red[tid*4+3];
            #pragma unroll
            for (int o = 4; o > 0; o >>= 1){
                a0 += __shfl_down_sync(0xffu, a0, o);
                a1 += __shfl_down_sync(0xffu, a1, o);
                a2 += __shfl_down_sync(0xffu, a2, o);
                a3 += __shfl_down_sync(0xffu, a3, o);
            }
            if (tid == 0){
                stats[6] = a3 + g_dscal;           // cb
                if (step > 0){
                    float p0 = a0 + bo[0], p1 = a1 + bo[1], p2 = a2 + bo[2];
                    size_t po = (size_t)b*(NSTEP*OUT) + (step - 1)*OUT;
                    out[po] = p0; out[po+1] = p1; out[po+2] = p2;
                    if (!last){
                        g_XT[512*B + b] = p0;
                        g_XT[513*B + b] = p1;
                        g_XT[514*B + b] = p2;
                    }
                }
            }
        }
    }

    if (last){
        if (tid < 256) out[HID_OFF + b*H + tid] = h;   // decoder_hidden
        return;
    }

    // ---- vq = P @ h + q, split across the 2 groups ----
    {
        float acc = (g == 0) ? g_q[lt] : 0.f;
        const int j0 = g*128;
        #pragma unroll 4
        for (int j = 0; j < 128; j++) acc += g_PT[(j0 + j)*H + lt] * hsm[j0 + j];
        sh512[tid] = acc;
    }
    __syncthreads();
    if (tid < 256) vq[tid] = sh512[tid] + sh512[tid + 256];
    __syncthreads();
    const float cb = stats[6];

    // ---- stream this group's half of enc[b]: 16 chunks x 16 rows, depth-3 ----
    const float4* src4 = (const float4*)(enc + (size_t)b*S*H + (size_t)g*256*H);
    float4* buf4 = (float4*)(sm + g*3*4096);
    const int bid = g + 1;   // named barrier id

    // prologue: issue chunks 0,1
    #pragma unroll
    for (int ch = 0; ch < 2; ch++){
        const float4* src = src4 + ch*1024;
        float4* dst = buf4 + ch*1024;
        #pragma unroll
        for (int i = 0; i < 4; i++) cpasync16(dst + lt + i*256, src + lt + i*256);
        cp_commit();
    }

    float ctx = 0.f, m = -1e30f, denom = 0.f;
    const int lw = wid & 7;              // warp index within group
    const float* groupbuf = sm + g*3*4096;

    for (int c = 0; c < 16; c++){
        if (c + 2 < 16){
            const float4* src = src4 + (c+2)*1024;
            float4* dst = buf4 + ((c+2)%3)*1024;
            #pragma unroll
            for (int i = 0; i < 4; i++) cpasync16(dst + lt + i*256, src + lt + i*256);
        }
        cp_commit();
        cp_wait2();
        barg(bid);
        const float* eb = groupbuf + (c%3)*4096;

        // scores: 16 rows, 2 per warp
        #pragma unroll
        for (int rr = 0; rr < 2; rr++){
            int sl = lw*2 + rr;
            const float* row = eb + sl*H;
            float d = 0.f;
            #pragma unroll
            for (int k = 0; k < 8; k++) d += row[lane + k*32] * vq[lane + k*32];
            #pragma unroll
            for (int o = 16; o > 0; o >>= 1) d += __shfl_down_sync(0xffffffffu, d, o);
            if (lane == 0) scores[g*256 + c*16 + sl] = d + cb;
        }
        barg(bid);

        // softmax stats for this chunk: first warp of group
        if (lw == 0){
            float v = (lane < 16) ? scores[g*256 + c*16 + lane] : -1e30f;
            #pragma unroll
            for (int o = 16; o > 0; o >>= 1) v = fmaxf(v, __shfl_xor_sync(0xffffffffu, v, o));
            float mn = fmaxf(m, v);
            float p = (lane < 16) ? expf(scores[g*256 + c*16 + lane] - mn) : 0.f;
            if (lane < 16) psm[g*16 + lane] = p;
            #pragma unroll
            for (int o = 16; o > 0; o >>= 1) p += __shfl_xor_sync(0xffffffffu, p, o);
            if (lane == 0){ red[g*2] = mn; red[g*2 + 1] = p; }
        }
        barg(bid);

        float mn = red[g*2], cs = red[g*2 + 1];
        float rs = expf(m - mn);
        ctx = ctx * rs;
        denom = denom * rs + cs;
        m = mn;

        // ctx: thread lt owns column lt
        float c0 = 0.f, c1 = 0.f;
        #pragma unroll
        for (int s = 0; s < 16; s += 2){
            c0 += psm[g*16 + s]     * eb[s*H + lt];
            c1 += psm[g*16 + s + 1] * eb[(s+1)*H + lt];
        }
        ctx += c0 + c1;
        barg(bid);   // protect buffer (c%3) before it is refilled next iter
    }

    // ---- merge the two groups' online-softmax states ----
    sh512[g*256 + lt] = ctx;
    if (lt == 0){ stats[g*2] = m; stats[g*2 + 1] = denom; }
    __syncthreads();
    if (tid < 256){
        float m0 = stats[0], d0 = stats[1], m1 = stats[2], d1 = stats[3];
        float M = fmaxf(m0, m1);
        float e0 = expf(m0 - M), e1 = expf(m1 - M);
        float inv = 1.f / (d0*e0 + d1*e1);
        float cx = (sh512[tid]*e0 + sh512[256 + tid]*e1) * inv;
        g_XT[tid*B + b] = cx;
        if (tid == 0){ stats[4] = M; stats[5] = inv; }
    }
    __syncthreads();
    float M = stats[4], inv = stats[5];
    size_t abase = (size_t)ATTN_OFF + ((size_t)b*NSTEP + step)*S;
    out[abase + tid] = expf(scores[tid] - M) * inv;
}

// ---------------- gates GEMM: C[r,b] = sum_k Wc[k,r] * XT[k,b], 8-way K split ----------------
// grid (16, 4, 8): 64x64 output tiles, z = K split. 256 threads, 4x4 microtile.
__global__ void __launch_bounds__(256) gates_gemm(){
    const int rt = blockIdx.x, bt = blockIdx.y, z = blockIdx.z;
    const int starts[9] = {0, 5, 9, 13, 17, 21, 25, 29, 33};
    const int t0 = starts[z], t1 = starts[z+1];

    __shared__ float As[2][16][68];
    __shared__ float Bs[2][16][68];

    const int tid = threadIdx.x;
    const int tx = tid & 15, ty = tid >> 4;
    const int lk = tid >> 4, lx = (tid & 15) * 4;

    float4 pa, pb;
    {
        int k = t0*16 + lk;
        pa = *(const float4*)&g_Wc[k*G4 + rt*64 + lx];
        pb = *(const float4*)&g_XT[k*B  + bt*64 + lx];
    }
    *(float4*)&As[0][lk][lx] = pa;
    *(float4*)&Bs[0][lk][lx] = pb;

    float acc[4][4];
    #pragma unroll
    for (int i = 0; i < 4; i++)
        #pragma unroll
        for (int j = 0; j < 4; j++) acc[i][j] = 0.f;

    const int nt = t1 - t0;
    for (int it = 0; it < nt; it++){
        __syncthreads();
        if (it + 1 < nt){
            int k = (t0 + it + 1)*16 + lk;
            pa = *(const float4*)&g_Wc[k*G4 + rt*64 + lx];
            pb = *(const float4*)&g_XT[k*B  + bt*64 + lx];
        }
        int cur = it & 1;
        #pragma unroll
        for (int kk = 0; kk < 16; kk++){
            float4 fa = *(float4*)&As[cur][kk][ty*4];
            float4 fb = *(float4*)&Bs[cur][kk][tx*4];
            acc[0][0] += fa.x*fb.x; acc[0][1] += fa.x*fb.y; acc[0][2] += fa.x*fb.z; acc[0][3] += fa.x*fb.w;
            acc[1][0] += fa.y*fb.x; acc[1][1] += fa.y*fb.y; acc[1][2] += fa.y*fb.z; acc[1][3] += fa.y*fb.w;
            acc[2][0] += fa.z*fb.x; acc[2][1] += fa.z*fb.y; acc[2][2] += fa.z*fb.z; acc[2][3] += fa.z*fb.w;
            acc[3][0] += fa.w*fb.x; acc[3][1] += fa.w*fb.y; acc[3][2] += fa.w*fb.z; acc[3][3] += fa.w*fb.w;
        }
        if (it + 1 < nt){
            int nxt = cur ^ 1;
            *(float4*)&As[nxt][lk][lx] = pa;
            *(float4*)&Bs[nxt][lk][lx] = pb;
        }
    }

    float* G = g_gates[z];
    const int r0 = rt*64 + ty*4;
    const int b0 = bt*64 + tx*4;
    #pragma unroll
    for (int j = 0; j < 4; j++){
        float4 v = make_float4(acc[0][j], acc[1][j], acc[2][j], acc[3][j]);
        if (z == 0){
            v.x += g_bias[r0];     v.y += g_bias[r0 + 1];
            v.z += g_bias[r0 + 2]; v.w += g_bias[r0 + 3];
        }
        *(float4*)&G[(size_t)(b0 + j)*G4 + r0] = v;
    }
}

// ---------------- launch ----------------
extern "C" void kernel_launch(void* const* d_in, const int* in_sizes, int n_in,
                              void* d_out, int out_size){
    const float* enc = (const float*)d_in[0];
    const float* eh  = (const float*)d_in[1];
    const float* ec  = (const float*)d_in[2];
    const float* Wa  = (const float*)d_in[3];
    const float* ba  = (const float*)d_in[4];
    const float* Ua  = (const float*)d_in[5];
    const float* bua = (const float*)d_in[6];
    const float* Wih = (const float*)d_in[7];
    const float* Whh = (const float*)d_in[8];
    const float* bih = (const float*)d_in[9];
    const float* bhh = (const float*)d_in[10];
    const float* Wo  = (const float*)d_in[11];
    const float* bo  = (const float*)d_in[12];
    float* out = (float*)d_out;

    cudaFuncSetAttribute(att_step, cudaFuncAttributeMaxDynamicSharedMemorySize, ATT_SMEM_BYTES);

    prep_pt<<<256, 256>>>(Wa, Ua);
    prep_vec<<<1, 256>>>(Wa, ba, Ua, bua);
    prep_pack<<<KP, 256>>>(Wih, Whh, bih, bhh);

    for (int step = 0; step <= NSTEP; step++){
        att_step<<<B, 512, ATT_SMEM_BYTES>>>(enc, eh, ec, Wo, bo, out, step, step == NSTEP);
        if (step < NSTEP){
            gates_gemm<<<dim3(16, 4, 8), 256>>>();
        }
    }
}

// round 4
// speedup vs baseline: 1.2815x; 1.1255x over previous
#include <cuda_runtime.h>
#include <cuda_bf16.h>
#include <math.h>

// Problem constants
#define B   256
#define S   512
#define H   256
#define OUT 3
#define NSTEP 64
#define G4  1024          // 4*H
#define INW 259           // OUT + H
#define KP  528           // padded K (515 -> 33 tiles of 16)
#define NSPLIT 8

#define PRED_SZ (B*NSTEP*OUT)          // 49152
#define HID_OFF PRED_SZ                // 49152
#define ATTN_OFF (PRED_SZ + B*H)       // 114688

// ---------------- scratch (device globals; no allocation) ----------------
__device__ float g_PT[H*H];        // P^T : PT[j*H + h] = sum_g Ua[g,h]*Wa[g,j]
__device__ float g_q[H];           // Ua^T @ ba
__device__ float g_Wc[KP*G4];      // packed weights, k-major: Wc[k*1024 + r]
__device__ float g_bias[G4];       // b_ih + b_hh
__device__ float g_XT[KP*B];       // X^T: rows 0..255 ctx, 256..511 h, 512..514 x_in, rest 0
__device__ float g_c[B*H];         // cell state
__device__ float g_gates[NSPLIT][B*G4]; // K-split partial gate buffers, layout [b*1024 + r]

// ---------------- helpers ----------------
__device__ __forceinline__ float sigmoidf_(float x){ return 1.f/(1.f+expf(-x)); }

// ---------------- precompute 1a: PT ----------------
__global__ void __launch_bounds__(256) prep_pt(const float* __restrict__ Wa,
                                               const float* __restrict__ Ua){
    int j = blockIdx.x, h = threadIdx.x;
    float acc = 0.f;
    for (int g = 0; g < H; g++) acc += Ua[g*H + h] * Wa[g*H + j];
    g_PT[j*H + h] = acc;
}

// ---------------- precompute 1b: q ----------------
__global__ void __launch_bounds__(256) prep_vec(const float* __restrict__ ba,
                                                const float* __restrict__ Ua){
    int h = threadIdx.x;
    float a = 0.f;
    for (int g = 0; g < H; g++) a += Ua[g*H + h] * ba[g];
    g_q[h] = a;
}

// ---------------- precompute 2: pack weights + bias + zero pads ----------------
__global__ void __launch_bounds__(256) prep_pack(const float* __restrict__ W_ih,
                                                 const float* __restrict__ W_hh,
                                                 const float* __restrict__ b_ih,
                                                 const float* __restrict__ b_hh){
    int k = blockIdx.x, t = threadIdx.x;
    #pragma unroll
    for (int m = 0; m < 4; m++){
        int r = t + m*256;
        float v;
        if (k < 256)      v = W_ih[r*INW + 3 + k];       // ctx part
        else if (k < 512) v = W_hh[r*H + (k - 256)];     // h part
        else if (k < 515) v = W_ih[r*INW + (k - 512)];   // x_in part
        else              v = 0.f;                       // pad
        g_Wc[k*G4 + r] = v;
    }
    if (k >= 515) g_XT[k*B + t] = 0.f;                   // zero pad rows of X^T
    if (k < 4){
        int r = k*256 + t;
        g_bias[r] = b_ih[r] + b_hh[r];
    }
}

// ---------------- ATT kernel ----------------
// grid = 256 (one block per batch), 512 threads = 16 warps.
// Warp-private online softmax; enc rows read straight from GMEM (no staging,
// no barriers in the streaming loop). One merge at the end.
__global__ void __launch_bounds__(512, 2) att_step(const float* __restrict__ enc,
                                                   const float* __restrict__ eh,
                                                   const float* __restrict__ ec,
                                                   const float* __restrict__ Wo,
                                                   const float* __restrict__ bo,
                                                   float* __restrict__ out,
                                                   int step, int last){
    __shared__ float scores[S];          // 512
    __shared__ float ctxbuf[16*H];       // 4096
    __shared__ float hsm[H];             // 256
    __shared__ float sh512[512];         // vq partials
    __shared__ float vqsm[H];            // 256
    __shared__ float red[64];
    __shared__ float mbuf[16], dbuf[16];

    const int tid  = threadIdx.x;
    const int w    = tid >> 5;           // warp 0..15
    const int lane = tid & 31;
    const int b    = blockIdx.x;

    // ---- Phase 0: LSTM cell (threads 0..255) ----
    float h = 0.f;
    if (tid < 256){
        if (step == 0){
            h = eh[b*H + tid];
            g_c[b*H + tid] = ec[b*H + tid];
            if (tid < 3) g_XT[(512 + tid)*B + b] = 0.f;   // x_in = SOS = 0
        } else {
            float zi = 0.f, zf = 0.f, zg = 0.f, zo = 0.f;
            #pragma unroll
            for (int z = 0; z < NSPLIT; z++){
                const float* G = g_gates[z] + b*G4 + tid;
                zi += G[0]; zf += G[256]; zg += G[512]; zo += G[768];
            }
            float co = g_c[b*H + tid];
            float cn = sigmoidf_(zf)*co + sigmoidf_(zi)*tanhf(zg);
            h = sigmoidf_(zo)*tanhf(cn);
            g_c[b*H + tid] = cn;
        }
        hsm[tid] = h;
        if (!last) g_XT[(256 + tid)*B + b] = h;
    }
    __syncthreads();

    // ---- pred = Wo @ h + bo  (previous step's output; feeds x_in) ----
    if (step > 0){
        float v0 = 0.f, v1 = 0.f, v2 = 0.f;
        if (tid < 256){
            v0 = Wo[tid]       * h;
            v1 = Wo[256 + tid] * h;
            v2 = Wo[512 + tid] * h;
        }
        #pragma unroll
        for (int o = 16; o > 0; o >>= 1){
            v0 += __shfl_down_sync(0xffffffffu, v0, o);
            v1 += __shfl_down_sync(0xffffffffu, v1, o);
            v2 += __shfl_down_sync(0xffffffffu, v2, o);
        }
        if (lane == 0){ red[w*4] = v0; red[w*4+1] = v1; red[w*4+2] = v2; red[w*4+3] = 0.f; }
        __syncthreads();
        if (tid < 8){
            float a0 = red[tid*4], a1 = red[tid*4+1], a2 = red[tid*4+2];
            #pragma unroll
            for (int o = 4; o > 0; o >>= 1){
                a0 += __shfl_down_sync(0xffu, a0, o);
                a1 += __shfl_down_sync(0xffu, a1, o);
                a2 += __shfl_down_sync(0xffu, a2, o);
            }
            if (tid == 0){
                float p0 = a0 + bo[0], p1 = a1 + bo[1], p2 = a2 + bo[2];
                size_t po = (size_t)b*(NSTEP*OUT) + (step - 1)*OUT;
                out[po] = p0; out[po+1] = p1; out[po+2] = p2;
                if (!last){
                    g_XT[512*B + b] = p0;
                    g_XT[513*B + b] = p1;
                    g_XT[514*B + b] = p2;
                }
            }
        }
    }

    if (last){
        if (tid < 256) out[HID_OFF + b*H + tid] = h;   // decoder_hidden
        return;
    }

    // ---- vq = P @ h + q, split across the 2 halves of the block ----
    {
        const int g2 = tid >> 8, lt = tid & 255;
        float acc = (g2 == 0) ? g_q[lt] : 0.f;
        const int j0 = g2*128;
        #pragma unroll 4
        for (int j = 0; j < 128; j++) acc += g_PT[(j0 + j)*H + lt] * hsm[j0 + j];
        sh512[tid] = acc;
    }
    __syncthreads();
    if (tid < 256) vqsm[tid] = sh512[tid] + sh512[tid + 256];
    __syncthreads();

    // per-lane vq registers: elems 4*lane..4*lane+3 and 128+4*lane..+3
    float4 vqa = *(const float4*)&vqsm[4*lane];
    float4 vqb = *(const float4*)&vqsm[128 + 4*lane];

    // ---- streaming loop: warp w handles rows c*32 + 2w, +1 ----
    const float4* rowbase = (const float4*)(enc + (size_t)b*S*H);
    float m = -1e30f, d = 0.f;
    float4 ctxa = make_float4(0.f,0.f,0.f,0.f);
    float4 ctxb = make_float4(0.f,0.f,0.f,0.f);

    #pragma unroll 2
    for (int c = 0; c < 16; c++){
        const int s0 = c*32 + w*2;
        const float4* r0 = rowbase + (size_t)s0*64;
        const float4* r1 = r0 + 64;
        float4 a0 = r0[lane], b0v = r0[32+lane];
        float4 a1 = r1[lane], b1v = r1[32+lane];

        float p0 = a0.x*vqa.x + a0.y*vqa.y + a0.z*vqa.z + a0.w*vqa.w
                 + b0v.x*vqb.x + b0v.y*vqb.y + b0v.z*vqb.z + b0v.w*vqb.w;
        float p1 = a1.x*vqa.x + a1.y*vqa.y + a1.z*vqa.z + a1.w*vqa.w
                 + b1v.x*vqb.x + b1v.y*vqb.y + b1v.z*vqb.z + b1v.w*vqb.w;
        #pragma unroll
        for (int o = 16; o > 0; o >>= 1){
            p0 += __shfl_xor_sync(0xffffffffu, p0, o);
            p1 += __shfl_xor_sync(0xffffffffu, p1, o);
        }
        if (lane == 0){ scores[s0] = p0; scores[s0+1] = p1; }

        float mn = fmaxf(m, fmaxf(p0, p1));
        float rs = __expf(m - mn);
        float e0 = __expf(p0 - mn);
        float e1 = __expf(p1 - mn);
        d = d*rs + e0 + e1;
        ctxa.x = ctxa.x*rs + e0*a0.x + e1*a1.x;
        ctxa.y = ctxa.y*rs + e0*a0.y + e1*a1.y;
        ctxa.z = ctxa.z*rs + e0*a0.z + e1*a1.z;
        ctxa.w = ctxa.w*rs + e0*a0.w + e1*a1.w;
        ctxb.x = ctxb.x*rs + e0*b0v.x + e1*b1v.x;
        ctxb.y = ctxb.y*rs + e0*b0v.y + e1*b1v.y;
        ctxb.z = ctxb.z*rs + e0*b0v.z + e1*b1v.z;
        ctxb.w = ctxb.w*rs + e0*b0v.w + e1*b1v.w;
        m = mn;
    }

    // ---- merge 16 warp-private states ----
    *(float4*)&ctxbuf[w*H + 4*lane]       = ctxa;
    *(float4*)&ctxbuf[w*H + 128 + 4*lane] = ctxb;
    if (lane == 0){ mbuf[w] = m; dbuf[w] = d; }
    __syncthreads();

    float M = -1e30f;
    #pragma unroll
    for (int i = 0; i < 16; i++) M = fmaxf(M, mbuf[i]);
    float D = 0.f;
    #pragma unroll
    for (int i = 0; i < 16; i++) D += dbuf[i] * __expf(mbuf[i] - M);
    float inv = 1.f / D;

    if (tid < 256){
        float cx = 0.f;
        #pragma unroll
        for (int i = 0; i < 16; i++) cx += ctxbuf[i*H + tid] * __expf(mbuf[i] - M);
        g_XT[tid*B + b] = cx * inv;
    }
    size_t abase = (size_t)ATTN_OFF + ((size_t)b*NSTEP + step)*S;
    out[abase + tid] = __expf(scores[tid] - M) * inv;
}

// ---------------- gates GEMM: C[r,b] = sum_k Wc[k,r] * XT[k,b], 8-way K split ----------------
// grid (16, 4, 8): 64x64 output tiles, z = K split. 256 threads, 4x4 microtile.
__global__ void __launch_bounds__(256) gates_gemm(){
    const int rt = blockIdx.x, bt = blockIdx.y, z = blockIdx.z;
    const int starts[9] = {0, 5, 9, 13, 17, 21, 25, 29, 33};
    const int t0 = starts[z], t1 = starts[z+1];

    __shared__ float As[2][16][68];
    __shared__ float Bs[2][16][68];

    const int tid = threadIdx.x;
    const int tx = tid & 15, ty = tid >> 4;
    const int lk = tid >> 4, lx = (tid & 15) * 4;

    float4 pa, pb;
    {
        int k = t0*16 + lk;
        pa = *(const float4*)&g_Wc[k*G4 + rt*64 + lx];
        pb = *(const float4*)&g_XT[k*B  + bt*64 + lx];
    }
    *(float4*)&As[0][lk][lx] = pa;
    *(float4*)&Bs[0][lk][lx] = pb;

    float acc[4][4];
    #pragma unroll
    for (int i = 0; i < 4; i++)
        #pragma unroll
        for (int j = 0; j < 4; j++) acc[i][j] = 0.f;

    const int nt = t1 - t0;
    for (int it = 0; it < nt; it++){
        __syncthreads();
        if (it + 1 < nt){
            int k = (t0 + it + 1)*16 + lk;
            pa = *(const float4*)&g_Wc[k*G4 + rt*64 + lx];
            pb = *(const float4*)&g_XT[k*B  + bt*64 + lx];
        }
        int cur = it & 1;
        #pragma unroll
        for (int kk = 0; kk < 16; kk++){
            float4 fa = *(float4*)&As[cur][kk][ty*4];
            float4 fb = *(float4*)&Bs[cur][kk][tx*4];
            acc[0][0] += fa.x*fb.x; acc[0][1] += fa.x*fb.y; acc[0][2] += fa.x*fb.z; acc[0][3] += fa.x*fb.w;
            acc[1][0] += fa.y*fb.x; acc[1][1] += fa.y*fb.y; acc[1][2] += fa.y*fb.z; acc[1][3] += fa.y*fb.w;
            acc[2][0] += fa.z*fb.x; acc[2][1] += fa.z*fb.y; acc[2][2] += fa.z*fb.z; acc[2][3] += fa.z*fb.w;
            acc[3][0] += fa.w*fb.x; acc[3][1] += fa.w*fb.y; acc[3][2] += fa.w*fb.z; acc[3][3] += fa.w*fb.w;
        }
        if (it + 1 < nt){
            int nxt = cur ^ 1;
            *(float4*)&As[nxt][lk][lx] = pa;
            *(float4*)&Bs[nxt][lk][lx] = pb;
        }
    }

    float* G = g_gates[z];
    const int r0 = rt*64 + ty*4;
    const int b0 = bt*64 + tx*4;
    #pragma unroll
    for (int j = 0; j < 4; j++){
        float4 v = make_float4(acc[0][j], acc[1][j], acc[2][j], acc[3][j]);
        if (z == 0){
            v.x += g_bias[r0];     v.y += g_bias[r0 + 1];
            v.z += g_bias[r0 + 2]; v.w += g_bias[r0 + 3];
        }
        *(float4*)&G[(size_t)(b0 + j)*G4 + r0] = v;
    }
}

// ---------------- launch ----------------
extern "C" void kernel_launch(void* const* d_in, const int* in_sizes, int n_in,
                              void* d_out, int out_size){
    const float* enc = (const float*)d_in[0];
    const float* eh  = (const float*)d_in[1];
    const float* ec  = (const float*)d_in[2];
    const float* Wa  = (const float*)d_in[3];
    const float* ba  = (const float*)d_in[4];
    const float* Ua  = (const float*)d_in[5];
    const float* Wih = (const float*)d_in[7];
    const float* Whh = (const float*)d_in[8];
    const float* bih = (const float*)d_in[9];
    const float* bhh = (const float*)d_in[10];
    const float* Wo  = (const float*)d_in[11];
    const float* bo  = (const float*)d_in[12];
    float* out = (float*)d_out;

    prep_pt<<<256, 256>>>(Wa, Ua);
    prep_vec<<<1, 256>>>(ba, Ua);
    prep_pack<<<KP, 256>>>(Wih, Whh, bih, bhh);

    for (int step = 0; step <= NSTEP; step++){
        att_step<<<B, 512>>>(enc, eh, ec, Wo, bo, out, step, step == NSTEP);
        if (step < NSTEP){
            gates_gemm<<<dim3(16, 4, 8), 256>>>();
        }
    }
}

// round 5
// speedup vs baseline: 1.3312x; 1.0388x over previous
#include <cuda_runtime.h>
#include <cuda_bf16.h>
#include <math.h>

// Problem constants
#define B   256
#define S   512
#define H   256
#define OUT 3
#define NSTEP 64
#define G4  1024          // 4*H
#define INW 259           // OUT + H
#define KP  528           // padded K (515 -> 33 tiles of 16)
#define NSPLIT 8

#define PRED_SZ (B*NSTEP*OUT)          // 49152
#define HID_OFF PRED_SZ                // 49152
#define ATTN_OFF (PRED_SZ + B*H)       // 114688

// ---------------- scratch (device globals; no allocation) ----------------
__device__ float g_P[H*H];         // P row-major: P[h*H + j] = sum_g Ua[g,h]*Wa[g,j]
__device__ float g_q[H];           // Ua^T @ ba
__device__ float g_Wc[KP*G4];      // packed weights, k-major: Wc[k*1024 + r]
__device__ float g_bias[G4];       // b_ih + b_hh
__device__ float g_XT[KP*B];       // X^T: rows 0..255 ctx, 256..511 h, 512..514 x_in, rest 0
__device__ float g_c[B*H];         // cell state
__device__ float g_gates[NSPLIT][B*G4]; // K-split partial gate buffers, layout [b*1024 + r]

// ---------------- helpers ----------------
__device__ __forceinline__ float sigmoidf_(float x){ return 1.f/(1.f+expf(-x)); }
__device__ __forceinline__ float dot4(float4 a, float4 b){
    return a.x*b.x + a.y*b.y + a.z*b.z + a.w*b.w;
}

// ---------------- precompute 1a: P (row-major) ----------------
__global__ void __launch_bounds__(256) prep_pt(const float* __restrict__ Wa,
                                               const float* __restrict__ Ua){
    int j = blockIdx.x, h = threadIdx.x;
    float acc = 0.f;
    for (int g = 0; g < H; g++) acc += Ua[g*H + h] * Wa[g*H + j];
    g_P[h*H + j] = acc;
}

// ---------------- precompute 1b: q ----------------
__global__ void __launch_bounds__(256) prep_vec(const float* __restrict__ ba,
                                                const float* __restrict__ Ua){
    int h = threadIdx.x;
    float a = 0.f;
    for (int g = 0; g < H; g++) a += Ua[g*H + h] * ba[g];
    g_q[h] = a;
}

// ---------------- precompute 2: pack weights + bias + zero pads ----------------
__global__ void __launch_bounds__(256) prep_pack(const float* __restrict__ W_ih,
                                                 const float* __restrict__ W_hh,
                                                 const float* __restrict__ b_ih,
                                                 const float* __restrict__ b_hh){
    int k = blockIdx.x, t = threadIdx.x;
    #pragma unroll
    for (int m = 0; m < 4; m++){
        int r = t + m*256;
        float v;
        if (k < 256)      v = W_ih[r*INW + 3 + k];       // ctx part
        else if (k < 512) v = W_hh[r*H + (k - 256)];     // h part
        else if (k < 515) v = W_ih[r*INW + (k - 512)];   // x_in part
        else              v = 0.f;                       // pad
        g_Wc[k*G4 + r] = v;
    }
    if (k >= 515) g_XT[k*B + t] = 0.f;                   // zero pad rows of X^T
    if (k < 4){
        int r = k*256 + t;
        g_bias[r] = b_ih[r] + b_hh[r];
    }
}

// ---------------- ATT kernel ----------------
// grid = 256 (one block per batch), 256 threads = 8 warps, 2 blocks/SM.
// Warp-private online softmax, 4 rows/iter, explicit register double-buffer
// prefetch (distance 1). Zero barriers in the streaming loop.
__global__ void __launch_bounds__(256, 2) att_step(const float* __restrict__ enc,
                                                   const float* __restrict__ eh,
                                                   const float* __restrict__ ec,
                                                   const float* __restrict__ Wo,
                                                   const float* __restrict__ bo,
                                                   float* __restrict__ out,
                                                   int step, int last){
    __shared__ __align__(16) float scores[S];     // 512
    __shared__ __align__(16) float ctxbuf[8*H];   // 2048
    __shared__ __align__(16) float hsm[H];        // 256
    __shared__ __align__(16) float vqsm[H];       // 256
    __shared__ float red[32];
    __shared__ float mbuf[8], dbuf[8];

    const int tid  = threadIdx.x;
    const int w    = tid >> 5;           // warp 0..7
    const int lane = tid & 31;
    const int b    = blockIdx.x;

    // ---- Phase 0: LSTM cell ----
    float h;
    if (step == 0){
        h = eh[b*H + tid];
        g_c[b*H + tid] = ec[b*H + tid];
        if (tid < 3) g_XT[(512 + tid)*B + b] = 0.f;   // x_in = SOS = 0
    } else {
        float zi = 0.f, zf = 0.f, zg = 0.f, zo = 0.f;
        #pragma unroll
        for (int z = 0; z < NSPLIT; z++){
            const float* G = g_gates[z] + b*G4 + tid;
            zi += G[0]; zf += G[256]; zg += G[512]; zo += G[768];
        }
        float co = g_c[b*H + tid];
        float cn = sigmoidf_(zf)*co + sigmoidf_(zi)*tanhf(zg);
        h = sigmoidf_(zo)*tanhf(cn);
        g_c[b*H + tid] = cn;
    }
    hsm[tid] = h;
    if (!last) g_XT[(256 + tid)*B + b] = h;
    __syncthreads();

    // ---- pred = Wo @ h + bo  (previous step's output; feeds x_in) ----
    if (step > 0){
        float v0 = Wo[tid] * h, v1 = Wo[256 + tid] * h, v2 = Wo[512 + tid] * h;
        #pragma unroll
        for (int o = 16; o > 0; o >>= 1){
            v0 += __shfl_down_sync(0xffffffffu, v0, o);
            v1 += __shfl_down_sync(0xffffffffu, v1, o);
            v2 += __shfl_down_sync(0xffffffffu, v2, o);
        }
        if (lane == 0){ red[w] = v0; red[8 + w] = v1; red[16 + w] = v2; }
        __syncthreads();
        if (tid == 0){
            float a0 = 0.f, a1 = 0.f, a2 = 0.f;
            #pragma unroll
            for (int i = 0; i < 8; i++){ a0 += red[i]; a1 += red[8+i]; a2 += red[16+i]; }
            float p0 = a0 + bo[0], p1 = a1 + bo[1], p2 = a2 + bo[2];
            size_t po = (size_t)b*(NSTEP*OUT) + (step - 1)*OUT;
            out[po] = p0; out[po+1] = p1; out[po+2] = p2;
            if (!last){
                g_XT[512*B + b] = p0;
                g_XT[513*B + b] = p1;
                g_XT[514*B + b] = p2;
            }
        }
    }

    if (last){
        out[HID_OFF + b*H + tid] = h;   // decoder_hidden
        return;
    }

    // ---- vq = P @ h + q  (per-thread row of P, vectorized LDG.128) ----
    {
        float a0 = g_q[tid], a1 = 0.f, a2 = 0.f, a3 = 0.f;
        const float4* Pr = (const float4*)(g_P + tid*H);
        const float4* hv4 = (const float4*)hsm;
        #pragma unroll 8
        for (int j4 = 0; j4 < 64; j4 += 4){
            a0 += dot4(Pr[j4],   hv4[j4]);
            a1 += dot4(Pr[j4+1], hv4[j4+1]);
            a2 += dot4(Pr[j4+2], hv4[j4+2]);
            a3 += dot4(Pr[j4+3], hv4[j4+3]);
        }
        vqsm[tid] = (a0 + a1) + (a2 + a3);
    }
    __syncthreads();

    // per-lane vq registers: elems 4*lane..+3 and 128+4*lane..+3
    const float4 vqa = *(const float4*)&vqsm[4*lane];
    const float4 vqb = *(const float4*)&vqsm[128 + 4*lane];

    // ---- streaming loop: warp w owns rows [w*64, w*64+64), 16 iters x 4 rows ----
    const float4* rowbase = (const float4*)(enc + (size_t)b*S*H) + (size_t)(w*64)*64;

    float4 A[2][4], Bv[2][4];
    #pragma unroll
    for (int r = 0; r < 4; r++){
        A[0][r]  = rowbase[r*64 + lane];
        Bv[0][r] = rowbase[r*64 + 32 + lane];
    }

    float m = -1e30f, d = 0.f;
    float4 ctxa = make_float4(0.f,0.f,0.f,0.f);
    float4 ctxb = make_float4(0.f,0.f,0.f,0.f);

    #pragma unroll
    for (int c = 0; c < 16; c++){
        const int cur = c & 1, nxt = cur ^ 1;
        // prefetch next 4 rows first (distance-1 register double buffer)
        if (c < 15){
            const float4* nb = rowbase + (c+1)*256;
            #pragma unroll
            for (int r = 0; r < 4; r++){
                A[nxt][r]  = nb[r*64 + lane];
                Bv[nxt][r] = nb[r*64 + 32 + lane];
            }
        }

        float p0 = dot4(A[cur][0], vqa) + dot4(Bv[cur][0], vqb);
        float p1 = dot4(A[cur][1], vqa) + dot4(Bv[cur][1], vqb);
        float p2 = dot4(A[cur][2], vqa) + dot4(Bv[cur][2], vqb);
        float p3 = dot4(A[cur][3], vqa) + dot4(Bv[cur][3], vqb);
        #pragma unroll
        for (int o = 16; o > 0; o >>= 1){
            p0 += __shfl_xor_sync(0xffffffffu, p0, o);
            p1 += __shfl_xor_sync(0xffffffffu, p1, o);
            p2 += __shfl_xor_sync(0xffffffffu, p2, o);
            p3 += __shfl_xor_sync(0xffffffffu, p3, o);
        }
        if (lane == 0) *(float4*)&scores[w*64 + c*4] = make_float4(p0, p1, p2, p3);

        float mn = fmaxf(m, fmaxf(fmaxf(p0, p1), fmaxf(p2, p3)));
        float rs = __expf(m - mn);
        float e0 = __expf(p0 - mn);
        float e1 = __expf(p1 - mn);
        float e2 = __expf(p2 - mn);
        float e3 = __expf(p3 - mn);
        d = d*rs + (e0 + e1) + (e2 + e3);
        ctxa.x = ctxa.x*rs + e0*A[cur][0].x + e1*A[cur][1].x + e2*A[cur][2].x + e3*A[cur][3].x;
        ctxa.y = ctxa.y*rs + e0*A[cur][0].y + e1*A[cur][1].y + e2*A[cur][2].y + e3*A[cur][3].y;
        ctxa.z = ctxa.z*rs + e0*A[cur][0].z + e1*A[cur][1].z + e2*A[cur][2].z + e3*A[cur][3].z;
        ctxa.w = ctxa.w*rs + e0*A[cur][0].w + e1*A[cur][1].w + e2*A[cur][2].w + e3*A[cur][3].w;
        ctxb.x = ctxb.x*rs + e0*Bv[cur][0].x + e1*Bv[cur][1].x + e2*Bv[cur][2].x + e3*Bv[cur][3].x;
        ctxb.y = ctxb.y*rs + e0*Bv[cur][0].y + e1*Bv[cur][1].y + e2*Bv[cur][2].y + e3*Bv[cur][3].y;
        ctxb.z = ctxb.z*rs + e0*Bv[cur][0].z + e1*Bv[cur][1].z + e2*Bv[cur][2].z + e3*Bv[cur][3].z;
        ctxb.w = ctxb.w*rs + e0*Bv[cur][0].w + e1*Bv[cur][1].w + e2*Bv[cur][2].w + e3*Bv[cur][3].w;
        m = mn;
    }

    // ---- merge 8 warp-private states ----
    *(float4*)&ctxbuf[w*H + 4*lane]       = ctxa;
    *(float4*)&ctxbuf[w*H + 128 + 4*lane] = ctxb;
    if (lane == 0){ mbuf[w] = m; dbuf[w] = d; }
    __syncthreads();

    float M = -1e30f;
    #pragma unroll
    for (int i = 0; i < 8; i++) M = fmaxf(M, mbuf[i]);
    float D = 0.f;
    float ew[8];
    #pragma unroll
    for (int i = 0; i < 8; i++){ ew[i] = __expf(mbuf[i] - M); D += dbuf[i] * ew[i]; }
    float inv = 1.f / D;

    {
        float cx = 0.f;
        #pragma unroll
        for (int i = 0; i < 8; i++) cx += ctxbuf[i*H + tid] * ew[i];
        g_XT[tid*B + b] = cx * inv;
    }
    size_t abase = (size_t)ATTN_OFF + ((size_t)b*NSTEP + step)*S;
    out[abase + tid]       = __expf(scores[tid]       - M) * inv;
    out[abase + tid + 256] = __expf(scores[tid + 256] - M) * inv;
}

// ---------------- gates GEMM: C[r,b] = sum_k Wc[k,r] * XT[k,b], 8-way K split ----------------
// grid (16, 4, 8): 64x64 output tiles, z = K split. 256 threads, 4x4 microtile.
__global__ void __launch_bounds__(256) gates_gemm(){
    const int rt = blockIdx.x, bt = blockIdx.y, z = blockIdx.z;
    const int starts[9] = {0, 5, 9, 13, 17, 21, 25, 29, 33};
    const int t0 = starts[z], t1 = starts[z+1];

    __shared__ float As[2][16][68];
    __shared__ float Bs[2][16][68];

    const int tid = threadIdx.x;
    const int tx = tid & 15, ty = tid >> 4;
    const int lk = tid >> 4, lx = (tid & 15) * 4;

    float4 pa, pb;
    {
        int k = t0*16 + lk;
        pa = *(const float4*)&g_Wc[k*G4 + rt*64 + lx];
        pb = *(const float4*)&g_XT[k*B  + bt*64 + lx];
    }
    *(float4*)&As[0][lk][lx] = pa;
    *(float4*)&Bs[0][lk][lx] = pb;

    float acc[4][4];
    #pragma unroll
    for (int i = 0; i < 4; i++)
        #pragma unroll
        for (int j = 0; j < 4; j++) acc[i][j] = 0.f;

    const int nt = t1 - t0;
    for (int it = 0; it < nt; it++){
        __syncthreads();
        if (it + 1 < nt){
            int k = (t0 + it + 1)*16 + lk;
            pa = *(const float4*)&g_Wc[k*G4 + rt*64 + lx];
            pb = *(const float4*)&g_XT[k*B  + bt*64 + lx];
        }
        int cur = it & 1;
        #pragma unroll
        for (int kk = 0; kk < 16; kk++){
            float4 fa = *(float4*)&As[cur][kk][ty*4];
            float4 fb = *(float4*)&Bs[cur][kk][tx*4];
            acc[0][0] += fa.x*fb.x; acc[0][1] += fa.x*fb.y; acc[0][2] += fa.x*fb.z; acc[0][3] += fa.x*fb.w;
            acc[1][0] += fa.y*fb.x; acc[1][1] += fa.y*fb.y; acc[1][2] += fa.y*fb.z; acc[1][3] += fa.y*fb.w;
            acc[2][0] += fa.z*fb.x; acc[2][1] += fa.z*fb.y; acc[2][2] += fa.z*fb.z; acc[2][3] += fa.z*fb.w;
            acc[3][0] += fa.w*fb.x; acc[3][1] += fa.w*fb.y; acc[3][2] += fa.w*fb.z; acc[3][3] += fa.w*fb.w;
        }
        if (it + 1 < nt){
            int nxt = cur ^ 1;
            *(float4*)&As[nxt][lk][lx] = pa;
            *(float4*)&Bs[nxt][lk][lx] = pb;
        }
    }

    float* G = g_gates[z];
    const int r0 = rt*64 + ty*4;
    const int b0 = bt*64 + tx*4;
    #pragma unroll
    for (int j = 0; j < 4; j++){
        float4 v = make_float4(acc[0][j], acc[1][j], acc[2][j], acc[3][j]);
        if (z == 0){
            v.x += g_bias[r0];     v.y += g_bias[r0 + 1];
            v.z += g_bias[r0 + 2]; v.w += g_bias[r0 + 3];
        }
        *(float4*)&G[(size_t)(b0 + j)*G4 + r0] = v;
    }
}

// ---------------- launch ----------------
extern "C" void kernel_launch(void* const* d_in, const int* in_sizes, int n_in,
                              void* d_out, int out_size){
    const float* enc = (const float*)d_in[0];
    const float* eh  = (const float*)d_in[1];
    const float* ec  = (const float*)d_in[2];
    const float* Wa  = (const float*)d_in[3];
    const float* ba  = (const float*)d_in[4];
    const float* Ua  = (const float*)d_in[5];
    const float* Wih = (const float*)d_in[7];
    const float* Whh = (const float*)d_in[8];
    const float* bih = (const float*)d_in[9];
    const float* bhh = (const float*)d_in[10];
    const float* Wo  = (const float*)d_in[11];
    const float* bo  = (const float*)d_in[12];
    float* out = (float*)d_out;

    prep_pt<<<256, 256>>>(Wa, Ua);
    prep_vec<<<1, 256>>>(ba, Ua);
    prep_pack<<<KP, 256>>>(Wih, Whh, bih, bhh);

    for (int step = 0; step <= NSTEP; step++){
        att_step<<<B, 256>>>(enc, eh, ec, Wo, bo, out, step, step == NSTEP);
        if (step < NSTEP){
            gates_gemm<<<dim3(16, 4, 8), 256>>>();
        }
    }
}